// round 13
// baseline (speedup 1.0000x reference)
#include <cuda_runtime.h>
#include <cuda_fp16.h>
#include <cstdint>

// ScaleDotProduct via mma.sync fp16 (HMMA): out = softmax(mask(Q K^T / 8)) V
// R13: identical math to R12 (3-term fp16 split on both GEMMs, ex2-folded
// softmax), but the tile body is fused into 4 per-16-key groups:
//   GEMM1(g) -> exp(g) -> pack(g) -> GEMM2(g)
// so GEMM2(g) MMAs can overlap exp(g+1)'s MUFU chain instead of all warps
// stalling in a synchronized softmax bubble once per tile.

#define SLEN 2048
#define HDIM 64
#define NHEADS 16
#define NBH 32
#define BQ 128
#define KT 64
#define NTILES (SLEN / KT)
#define NTHREADS 256
#define MASK_WORDS (2 * SLEN * (SLEN / 32))
#define ROWU4 8                       // 64 fp16 = 128B = 8 uint4 per row
#define NROWCHUNKS (NBH * SLEN * ROWU4)

__device__ unsigned int g_maskbits[MASK_WORDS];
__device__ __align__(16) uint4 gQhi[NROWCHUNKS], gQlo[NROWCHUNKS];
__device__ __align__(16) uint4 gKhi[NROWCHUNKS], gKlo[NROWCHUNKS];
__device__ __align__(16) uint4 gVhi[NROWCHUNKS], gVlo[NROWCHUNKS];

// stage = {Khi@0, Klo@8K, Vhi@16K, Vlo@24K} = 32KB; two stages.
#define STAGE 32768
#define SM_TOTAL 65536

#define SWZ(o) ((o) ^ ((((uint32_t)(o)) >> 3) & 0x70))

__device__ __forceinline__ uint32_t smem_u32(const void* p) {
    uint32_t a;
    asm("{ .reg .u64 t; cvta.to.shared.u64 t, %1; cvt.u32.u64 %0, t; }"
        : "=r"(a) : "l"(p));
    return a;
}
__device__ __forceinline__ void ldsm_x4(uint32_t addr, uint32_t r[4]) {
    asm volatile("ldmatrix.sync.aligned.m8n8.x4.shared.b16 {%0,%1,%2,%3}, [%4];"
        : "=r"(r[0]), "=r"(r[1]), "=r"(r[2]), "=r"(r[3]) : "r"(addr));
}
__device__ __forceinline__ void ldsm_x4t(uint32_t addr, uint32_t r[4]) {
    asm volatile("ldmatrix.sync.aligned.m8n8.x4.trans.shared.b16 {%0,%1,%2,%3}, [%4];"
        : "=r"(r[0]), "=r"(r[1]), "=r"(r[2]), "=r"(r[3]) : "r"(addr));
}
__device__ __forceinline__ void mma_f16(float d[4], const uint32_t a[4],
                                        uint32_t b0, uint32_t b1) {
    asm volatile(
        "mma.sync.aligned.m16n8k16.row.col.f32.f16.f16.f32 "
        "{%0,%1,%2,%3}, {%4,%5,%6,%7}, {%8,%9}, {%0,%1,%2,%3};"
        : "+f"(d[0]), "+f"(d[1]), "+f"(d[2]), "+f"(d[3])
        : "r"(a[0]), "r"(a[1]), "r"(a[2]), "r"(a[3]), "r"(b0), "r"(b1));
}
__device__ __forceinline__ void cpa16(uint32_t dst, const void* src) {
    asm volatile("cp.async.cg.shared.global [%0], [%1], 16;"
                 :: "r"(dst), "l"(src) : "memory");
}
#define CP_COMMIT() asm volatile("cp.async.commit_group;" ::: "memory")
#define CP_WAIT0()  asm volatile("cp.async.wait_group 0;" ::: "memory")
#define CP_WAIT1()  asm volatile("cp.async.wait_group 1;" ::: "memory")

__device__ __forceinline__ float ex2(float x) {
    float r;
    asm("ex2.approx.f32 %0, %1;" : "=f"(r) : "f"(x));
    return r;
}
__device__ __forceinline__ uint32_t pkf16(float a, float b) {
    uint32_t r;
    asm("cvt.rn.f16x2.f32 %0, %1, %2;" : "=r"(r) : "f"(b), "f"(a));
    return r;
}
__device__ __forceinline__ uint32_t pkf16_lo(float a, float b, uint32_t h) {
    float ha, hb;
    asm("{ .reg .f16 x, y; mov.b32 {x, y}, %2;"
        " cvt.f32.f16 %0, x; cvt.f32.f16 %1, y; }"
        : "=f"(ha), "=f"(hb) : "r"(h));
    return pkf16(a - ha, b - hb);
}
__device__ __forceinline__ void split_f16(float x, unsigned short& h,
                                          unsigned short& l) {
    __half hb = __float2half_rn(x);
    float hf = __half2float(hb);
    __half lb = __float2half_rn(x - hf);
    h = *(unsigned short*)&hb;
    l = *(unsigned short*)&lb;
}
__device__ __forceinline__ uint32_t pk2(unsigned short a, unsigned short b) {
    return (uint32_t)a | ((uint32_t)b << 16);
}

// ---------- pre-pass 1: mask int32 -> bits ----------
__global__ void pack_mask_kernel(const int* __restrict__ M) {
    int w = blockIdx.x * blockDim.x + threadIdx.x;
    if (w >= MASK_WORDS) return;
    const uint4* s4 = (const uint4*)(M + (size_t)w * 32);
    unsigned int bits = 0;
    #pragma unroll
    for (int j = 0; j < 8; j++) {
        uint4 t = s4[j];
        bits |= (t.x ? 1u : 0u) << (4 * j);
        bits |= (t.y ? 1u : 0u) << (4 * j + 1);
        bits |= (t.z ? 1u : 0u) << (4 * j + 2);
        bits |= (t.w ? 1u : 0u) << (4 * j + 3);
    }
    g_maskbits[w] = bits;
}

// ---------- pre-pass 2: fp32 -> fp16 hi/lo swizzled images ----------
__global__ void presplit_kernel(const float* __restrict__ Q,
                                const float* __restrict__ K,
                                const float* __restrict__ V) {
    int idx = blockIdx.x * blockDim.x + threadIdx.x;
    if (idx >= NROWCHUNKS) return;
    int rg = idx >> 3;
    int c  = idx & 7;
    const float* src;
    uint4 *dh, *dl;
    float sc;
    if (blockIdx.y == 0)      { src = Q; dh = gQhi; dl = gQlo; sc = 0.125f * 1.44269504f; }
    else if (blockIdx.y == 1) { src = K; dh = gKhi; dl = gKlo; sc = 1.0f; }
    else                      { src = V; dh = gVhi; dl = gVlo; sc = 1.0f; }
    const float4* s4 = (const float4*)(src + (size_t)rg * HDIM + c * 8);
    float4 a = s4[0], b = s4[1];
    float v[8] = {a.x*sc, a.y*sc, a.z*sc, a.w*sc, b.x*sc, b.y*sc, b.z*sc, b.w*sc};
    unsigned short h[8], l[8];
    #pragma unroll
    for (int j = 0; j < 8; j++) split_f16(v[j], h[j], l[j]);
    int cs = c ^ (rg & 7);        // matches smem SWZ
    dh[(size_t)rg * 8 + cs] = make_uint4(pk2(h[0],h[1]), pk2(h[2],h[3]),
                                         pk2(h[4],h[5]), pk2(h[6],h[7]));
    dl[(size_t)rg * 8 + cs] = make_uint4(pk2(l[0],l[1]), pk2(l[2],l[3]),
                                         pk2(l[4],l[5]), pk2(l[6],l[7]));
}

// ---------- main kernel ----------
__global__ __launch_bounds__(NTHREADS, 2)
void sdpa_mma_kernel(float* __restrict__ O)
{
    extern __shared__ __align__(128) char smem[];
    const uint32_t sb = smem_u32(smem);
    const int tid  = threadIdx.x;
    const int lane = tid & 31;
    const int wid  = tid >> 5;

    const int bh = blockIdx.x;
    const int qt = blockIdx.y;
    const size_t rowbase = (size_t)bh * SLEN;

    // ---- prologue: Qhi->buf0, Qlo->buf1 ----
    {
        const uint4* qh = gQhi + (rowbase + (size_t)qt * BQ) * ROWU4;
        const uint4* ql = gQlo + (rowbase + (size_t)qt * BQ) * ROWU4;
        #pragma unroll
        for (int j = 0; j < 4; j++) {
            int i = tid + j * NTHREADS;
            cpa16(sb + i * 16,         qh + i);
            cpa16(sb + STAGE + i * 16, ql + i);
        }
        CP_COMMIT();
        CP_WAIT0();
        __syncthreads();
    }

    // ---- Q A-fragments (constant across tiles) ----
    uint32_t qfh[4][4], qfl[4][4];
    {
        int qr = wid * 16 + (lane & 15);
        uint32_t cb = (uint32_t)((lane >> 4) * 16);
        #pragma unroll
        for (int kc = 0; kc < 4; kc++) {
            uint32_t off = (uint32_t)(qr * 128 + kc * 32) + cb;
            ldsm_x4(sb + SWZ(off), qfh[kc]);
            ldsm_x4(sb + STAGE + SWZ(off), qfl[kc]);
        }
    }
    __syncthreads();

    // prefetch tile0 -> buf0, tile1 -> buf1 (separate groups)
    #pragma unroll
    for (int tt = 0; tt < 2; tt++) {
        size_t rb = (rowbase + (size_t)tt * KT) * ROWU4;
        uint32_t db = sb + (uint32_t)(tt * STAGE);
        #pragma unroll
        for (int j = 0; j < 2; j++) {
            int i = tid + j * NTHREADS;
            cpa16(db + i * 16,         gKhi + rb + i);
            cpa16(db + 8192 + i * 16,  gKlo + rb + i);
            cpa16(db + 16384 + i * 16, gVhi + rb + i);
            cpa16(db + 24576 + i * 16, gVlo + rb + i);
        }
        CP_COMMIT();
    }
    CP_WAIT1();
    __syncthreads();

    float o[8][4];
    #pragma unroll
    for (int n = 0; n < 8; n++)
        #pragma unroll
        for (int i = 0; i < 4; i++) o[n][i] = 0.0f;
    float lsum0 = 0.0f, lsum1 = 0.0f;

    const int row0 = qt * BQ + wid * 16 + (lane >> 2);
    const unsigned int* mw0 = g_maskbits
        + (size_t)(bh / NHEADS) * SLEN * (SLEN / 32) + (size_t)row0 * (SLEN / 32);
    const unsigned int* mw1 = mw0 + 8 * (SLEN / 32);

    const int krow = (lane & 7) + ((lane >> 4) << 3);
    const uint32_t kcb = (uint32_t)(((lane >> 3) & 1) * 16);
    const int vrow = lane & 15;
    const uint32_t vcb = (uint32_t)((lane >> 4) * 16);
    const int cb2 = (lane & 3) * 2;

    for (int t = 0; t < NTILES; t++) {
        const uint32_t bK = sb + (uint32_t)((t & 1) * STAGE);
        const uint32_t bKl = bK + 8192, bV = bK + 16384, bVl = bK + 24576;
        const unsigned int ma0 = mw0[t*2], mb0t = mw0[t*2+1];
        const unsigned int ma1 = mw1[t*2], mb1t = mw1[t*2+1];

        // ---- fused per-16-key groups: GEMM1(g) -> exp -> pack -> GEMM2(g) ----
        #pragma unroll
        for (int g = 0; g < 4; g++) {
            // GEMM1 group g: S rows x keys [16g,16g+16)
            float s0[4] = {0.f, 0.f, 0.f, 0.f};
            float s1[4] = {0.f, 0.f, 0.f, 0.f};
            #pragma unroll
            for (int kc = 0; kc < 4; kc++) {
                uint32_t off = (uint32_t)((g * 16 + krow) * 128 + kc * 32) + kcb;
                uint32_t kb[4], kl[4];
                ldsm_x4(bK + SWZ(off), kb);
                ldsm_x4(bKl + SWZ(off), kl);
                mma_f16(s0, qfh[kc], kb[0], kb[1]);
                mma_f16(s0, qfh[kc], kl[0], kl[1]);
                mma_f16(s0, qfl[kc], kb[0], kb[1]);
                mma_f16(s1, qfh[kc], kb[2], kb[3]);
                mma_f16(s1, qfh[kc], kl[2], kl[3]);
                mma_f16(s1, qfl[kc], kb[2], kb[3]);
            }

            // mask + exp2 for this group's 16 columns
            const unsigned int w0 = (g < 2) ? ma0 : mb0t;
            const unsigned int w1 = (g < 2) ? ma1 : mb1t;
            const int sh0 = (g * 16 + cb2) & 31;        // cols 16g+cb2
            const int sh1 = (g * 16 + 8 + cb2) & 31;    // cols 16g+8+cb2
            float p0[4], p1[4];
            p0[0] = ((w0 >> sh0)       & 1u) ? 0.0f : ex2(s0[0]);
            p0[1] = ((w0 >> (sh0 + 1)) & 1u) ? 0.0f : ex2(s0[1]);
            p0[2] = ((w1 >> sh0)       & 1u) ? 0.0f : ex2(s0[2]);
            p0[3] = ((w1 >> (sh0 + 1)) & 1u) ? 0.0f : ex2(s0[3]);
            p1[0] = ((w0 >> sh1)       & 1u) ? 0.0f : ex2(s1[0]);
            p1[1] = ((w0 >> (sh1 + 1)) & 1u) ? 0.0f : ex2(s1[1]);
            p1[2] = ((w1 >> sh1)       & 1u) ? 0.0f : ex2(s1[2]);
            p1[3] = ((w1 >> (sh1 + 1)) & 1u) ? 0.0f : ex2(s1[3]);
            lsum0 += (p0[0] + p0[1]) + (p1[0] + p1[1]);
            lsum1 += (p0[2] + p0[3]) + (p1[2] + p1[3]);

            // pack P group -> A-fragments (hi + residual)
            uint32_t ah[4], al[4];
            ah[0] = pkf16(p0[0], p0[1]);  al[0] = pkf16_lo(p0[0], p0[1], ah[0]);
            ah[1] = pkf16(p0[2], p0[3]);  al[1] = pkf16_lo(p0[2], p0[3], ah[1]);
            ah[2] = pkf16(p1[0], p1[1]);  al[2] = pkf16_lo(p1[0], p1[1], ah[2]);
            ah[3] = pkf16(p1[2], p1[3]);  al[3] = pkf16_lo(p1[2], p1[3], ah[3]);

            // GEMM2 group g: O += P[:,16g:16g+16] V[16g:16g+16,:]
            #pragma unroll
            for (int dp = 0; dp < 4; dp++) {
                uint32_t off = (uint32_t)((g * 16 + vrow) * 128 + dp * 32) + vcb;
                uint32_t vh[4], vl[4];
                ldsm_x4t(bV + SWZ(off), vh);
                ldsm_x4t(bVl + SWZ(off), vl);
                mma_f16(o[2*dp],   ah, vh[0], vh[1]);
                mma_f16(o[2*dp],   ah, vl[0], vl[1]);
                mma_f16(o[2*dp],   al, vh[0], vh[1]);
                mma_f16(o[2*dp+1], ah, vh[2], vh[3]);
                mma_f16(o[2*dp+1], ah, vl[2], vl[3]);
                mma_f16(o[2*dp+1], al, vh[2], vh[3]);
            }
        }

        __syncthreads();                        // done reading buf[t&1]
        if (t + 2 < NTILES) {                   // prefetch t+2 into buf[t&1]
            size_t rb = (rowbase + (size_t)(t + 2) * KT) * ROWU4;
            uint32_t db = sb + (uint32_t)((t & 1) * STAGE);
            #pragma unroll
            for (int j = 0; j < 2; j++) {
                int i = tid + j * NTHREADS;
                cpa16(db + i * 16,         gKhi + rb + i);
                cpa16(db + 8192 + i * 16,  gKlo + rb + i);
                cpa16(db + 16384 + i * 16, gVhi + rb + i);
                cpa16(db + 24576 + i * 16, gVlo + rb + i);
            }
        }
        CP_COMMIT();
        CP_WAIT1();                             // tile t+1 complete
        __syncthreads();
    }

    // ---- epilogue ----
    lsum0 += __shfl_xor_sync(0xffffffffu, lsum0, 1);
    lsum0 += __shfl_xor_sync(0xffffffffu, lsum0, 2);
    lsum1 += __shfl_xor_sync(0xffffffffu, lsum1, 1);
    lsum1 += __shfl_xor_sync(0xffffffffu, lsum1, 2);
    const float inv0 = (lsum0 > 0.0f) ? (1.0f / lsum0) : 0.0f;   // fully masked -> 0
    const float inv1 = (lsum1 > 0.0f) ? (1.0f / lsum1) : 0.0f;

    float* Ob = O + (size_t)bh * SLEN * HDIM;
    const int r0 = qt * BQ + wid * 16 + (lane >> 2);
    const int r1 = r0 + 8;
    #pragma unroll
    for (int n = 0; n < 8; n++) {
        int col = n * 8 + (lane & 3) * 2;
        *(float2*)(Ob + (size_t)r0 * HDIM + col) =
            make_float2(o[n][0] * inv0, o[n][1] * inv0);
        *(float2*)(Ob + (size_t)r1 * HDIM + col) =
            make_float2(o[n][2] * inv1, o[n][3] * inv1);
    }
}

extern "C" void kernel_launch(void* const* d_in, const int* in_sizes, int n_in,
                              void* d_out, int out_size)
{
    (void)in_sizes; (void)n_in; (void)out_size;
    const float* Q = (const float*)d_in[0];
    const float* K = (const float*)d_in[1];
    const float* V = (const float*)d_in[2];
    const int*   M = (const int*)d_in[3];
    float*       O = (float*)d_out;

    cudaFuncSetAttribute(sdpa_mma_kernel,
                         cudaFuncAttributeMaxDynamicSharedMemorySize, SM_TOTAL);

    pack_mask_kernel<<<MASK_WORDS / 256, 256>>>(M);
    dim3 pg(NROWCHUNKS / 256, 3);
    presplit_kernel<<<pg, 256>>>(Q, K, V);
    dim3 grid(NBH, SLEN / BQ);
    sdpa_mma_kernel<<<grid, NTHREADS, SM_TOTAL>>>(O);
}

// round 14
// speedup vs baseline: 1.9148x; 1.9148x over previous
#include <cuda_runtime.h>
#include <cuda_fp16.h>
#include <cstdint>

// ScaleDotProduct via mma.sync fp16 (HMMA): out = softmax(mask(Q K^T / 8)) V
// R14: R12's proven monolithic-phase structure (R13's fusion destroyed ILP and
// regressed 47%). GEMM1 stays 3-term (Qh·Kh + Qh·Kl + Ql·Kh). GEMM2 drops to
// the single Ph·Vh term: fp16 residuals are 2^-12-relative, and the R11-
// calibrated cost of a dropped term is ~2.3e-4 each -> ~3.4e-4 total vs the
// 1e-3 threshold. ex2-folded softmax; cp.async double-buffered 24KB stages.

#define SLEN 2048
#define HDIM 64
#define NHEADS 16
#define NBH 32
#define BQ 128
#define KT 64
#define NTILES (SLEN / KT)
#define NTHREADS 256
#define MASK_WORDS (2 * SLEN * (SLEN / 32))
#define ROWU4 8                       // 64 fp16 = 128B = 8 uint4 per row
#define NROWCHUNKS (NBH * SLEN * ROWU4)

__device__ unsigned int g_maskbits[MASK_WORDS];
__device__ __align__(16) uint4 gQhi[NROWCHUNKS], gQlo[NROWCHUNKS];
__device__ __align__(16) uint4 gKhi[NROWCHUNKS], gKlo[NROWCHUNKS];
__device__ __align__(16) uint4 gVhi[NROWCHUNKS];

// stage = {Khi@0, Klo@8K, Vhi@16K} = 24KB; two stages.
#define STAGE 24576
#define SM_TOTAL 49152

#define SWZ(o) ((o) ^ ((((uint32_t)(o)) >> 3) & 0x70))

__device__ __forceinline__ uint32_t smem_u32(const void* p) {
    uint32_t a;
    asm("{ .reg .u64 t; cvta.to.shared.u64 t, %1; cvt.u32.u64 %0, t; }"
        : "=r"(a) : "l"(p));
    return a;
}
__device__ __forceinline__ void ldsm_x4(uint32_t addr, uint32_t r[4]) {
    asm volatile("ldmatrix.sync.aligned.m8n8.x4.shared.b16 {%0,%1,%2,%3}, [%4];"
        : "=r"(r[0]), "=r"(r[1]), "=r"(r[2]), "=r"(r[3]) : "r"(addr));
}
__device__ __forceinline__ void ldsm_x4t(uint32_t addr, uint32_t r[4]) {
    asm volatile("ldmatrix.sync.aligned.m8n8.x4.trans.shared.b16 {%0,%1,%2,%3}, [%4];"
        : "=r"(r[0]), "=r"(r[1]), "=r"(r[2]), "=r"(r[3]) : "r"(addr));
}
__device__ __forceinline__ void mma_f16(float d[4], const uint32_t a[4],
                                        uint32_t b0, uint32_t b1) {
    asm volatile(
        "mma.sync.aligned.m16n8k16.row.col.f32.f16.f16.f32 "
        "{%0,%1,%2,%3}, {%4,%5,%6,%7}, {%8,%9}, {%0,%1,%2,%3};"
        : "+f"(d[0]), "+f"(d[1]), "+f"(d[2]), "+f"(d[3])
        : "r"(a[0]), "r"(a[1]), "r"(a[2]), "r"(a[3]), "r"(b0), "r"(b1));
}
__device__ __forceinline__ void cpa16(uint32_t dst, const void* src) {
    asm volatile("cp.async.cg.shared.global [%0], [%1], 16;"
                 :: "r"(dst), "l"(src) : "memory");
}
#define CP_COMMIT() asm volatile("cp.async.commit_group;" ::: "memory")
#define CP_WAIT0()  asm volatile("cp.async.wait_group 0;" ::: "memory")
#define CP_WAIT1()  asm volatile("cp.async.wait_group 1;" ::: "memory")

__device__ __forceinline__ float ex2(float x) {
    float r;
    asm("ex2.approx.f32 %0, %1;" : "=f"(r) : "f"(x));
    return r;
}
__device__ __forceinline__ uint32_t pkf16(float a, float b) {
    uint32_t r;
    asm("cvt.rn.f16x2.f32 %0, %1, %2;" : "=r"(r) : "f"(b), "f"(a));
    return r;
}
__device__ __forceinline__ void split_f16(float x, unsigned short& h,
                                          unsigned short& l) {
    __half hb = __float2half_rn(x);
    float hf = __half2float(hb);
    __half lb = __float2half_rn(x - hf);
    h = *(unsigned short*)&hb;
    l = *(unsigned short*)&lb;
}
__device__ __forceinline__ uint32_t pk2(unsigned short a, unsigned short b) {
    return (uint32_t)a | ((uint32_t)b << 16);
}

// ---------- pre-pass 1: mask int32 -> bits ----------
__global__ void pack_mask_kernel(const int* __restrict__ M) {
    int w = blockIdx.x * blockDim.x + threadIdx.x;
    if (w >= MASK_WORDS) return;
    const uint4* s4 = (const uint4*)(M + (size_t)w * 32);
    unsigned int bits = 0;
    #pragma unroll
    for (int j = 0; j < 8; j++) {
        uint4 t = s4[j];
        bits |= (t.x ? 1u : 0u) << (4 * j);
        bits |= (t.y ? 1u : 0u) << (4 * j + 1);
        bits |= (t.z ? 1u : 0u) << (4 * j + 2);
        bits |= (t.w ? 1u : 0u) << (4 * j + 3);
    }
    g_maskbits[w] = bits;
}

// ---------- pre-pass 2: fp32 -> fp16 hi/lo swizzled images ----------
// Q pre-scaled by (1/8)*log2(e) so softmax is a bare ex2. V stores hi only.
__global__ void presplit_kernel(const float* __restrict__ Q,
                                const float* __restrict__ K,
                                const float* __restrict__ V) {
    int idx = blockIdx.x * blockDim.x + threadIdx.x;
    if (idx >= NROWCHUNKS) return;
    int rg = idx >> 3;
    int c  = idx & 7;
    const float* src;
    uint4 *dh, *dl;
    float sc;
    if (blockIdx.y == 0)      { src = Q; dh = gQhi; dl = gQlo; sc = 0.125f * 1.44269504f; }
    else if (blockIdx.y == 1) { src = K; dh = gKhi; dl = gKlo; sc = 1.0f; }
    else                      { src = V; dh = gVhi; dl = 0;    sc = 1.0f; }
    const float4* s4 = (const float4*)(src + (size_t)rg * HDIM + c * 8);
    float4 a = s4[0], b = s4[1];
    float v[8] = {a.x*sc, a.y*sc, a.z*sc, a.w*sc, b.x*sc, b.y*sc, b.z*sc, b.w*sc};
    unsigned short h[8], l[8];
    #pragma unroll
    for (int j = 0; j < 8; j++) split_f16(v[j], h[j], l[j]);
    int cs = c ^ (rg & 7);        // matches smem SWZ
    dh[(size_t)rg * 8 + cs] = make_uint4(pk2(h[0],h[1]), pk2(h[2],h[3]),
                                         pk2(h[4],h[5]), pk2(h[6],h[7]));
    if (dl)
        dl[(size_t)rg * 8 + cs] = make_uint4(pk2(l[0],l[1]), pk2(l[2],l[3]),
                                             pk2(l[4],l[5]), pk2(l[6],l[7]));
}

// ---------- main kernel ----------
__global__ __launch_bounds__(NTHREADS, 2)
void sdpa_mma_kernel(float* __restrict__ O)
{
    extern __shared__ __align__(128) char smem[];
    const uint32_t sb = smem_u32(smem);
    const int tid  = threadIdx.x;
    const int lane = tid & 31;
    const int wid  = tid >> 5;

    const int bh = blockIdx.x;
    const int qt = blockIdx.y;
    const size_t rowbase = (size_t)bh * SLEN;

    // ---- prologue: Qhi->buf0, Qlo->buf1 ----
    {
        const uint4* qh = gQhi + (rowbase + (size_t)qt * BQ) * ROWU4;
        const uint4* ql = gQlo + (rowbase + (size_t)qt * BQ) * ROWU4;
        #pragma unroll
        for (int j = 0; j < 4; j++) {
            int i = tid + j * NTHREADS;
            cpa16(sb + i * 16,         qh + i);
            cpa16(sb + STAGE + i * 16, ql + i);
        }
        CP_COMMIT();
        CP_WAIT0();
        __syncthreads();
    }

    // ---- Q A-fragments (constant across tiles) ----
    uint32_t qfh[4][4], qfl[4][4];
    {
        int qr = wid * 16 + (lane & 15);
        uint32_t cb = (uint32_t)((lane >> 4) * 16);
        #pragma unroll
        for (int kc = 0; kc < 4; kc++) {
            uint32_t off = (uint32_t)(qr * 128 + kc * 32) + cb;
            ldsm_x4(sb + SWZ(off), qfh[kc]);
            ldsm_x4(sb + STAGE + SWZ(off), qfl[kc]);
        }
    }
    __syncthreads();

    // prefetch tile0 -> buf0, tile1 -> buf1 (separate groups)
    #pragma unroll
    for (int tt = 0; tt < 2; tt++) {
        size_t rb = (rowbase + (size_t)tt * KT) * ROWU4;
        uint32_t db = sb + (uint32_t)(tt * STAGE);
        #pragma unroll
        for (int j = 0; j < 2; j++) {
            int i = tid + j * NTHREADS;
            cpa16(db + i * 16,         gKhi + rb + i);
            cpa16(db + 8192 + i * 16,  gKlo + rb + i);
            cpa16(db + 16384 + i * 16, gVhi + rb + i);
        }
        CP_COMMIT();
    }
    CP_WAIT1();
    __syncthreads();

    float o[8][4];
    #pragma unroll
    for (int n = 0; n < 8; n++)
        #pragma unroll
        for (int i = 0; i < 4; i++) o[n][i] = 0.0f;
    float lsum0 = 0.0f, lsum1 = 0.0f;

    const int row0 = qt * BQ + wid * 16 + (lane >> 2);
    const unsigned int* mw0 = g_maskbits
        + (size_t)(bh / NHEADS) * SLEN * (SLEN / 32) + (size_t)row0 * (SLEN / 32);
    const unsigned int* mw1 = mw0 + 8 * (SLEN / 32);

    const int krow = (lane & 7) + ((lane >> 4) << 3);
    const uint32_t kcb = (uint32_t)(((lane >> 3) & 1) * 16);
    const int vrow = lane & 15;
    const uint32_t vcb = (uint32_t)((lane >> 4) * 16);

    for (int t = 0; t < NTILES; t++) {
        const uint32_t bK = sb + (uint32_t)((t & 1) * STAGE);
        const uint32_t bKl = bK + 8192, bV = bK + 16384;

        // ---- GEMM1: S = Qh·Kh + Qh·Kl + Ql·Kh (3-term, fp16 residuals) ----
        float s[8][4];
        #pragma unroll
        for (int n = 0; n < 8; n++)
            #pragma unroll
            for (int i = 0; i < 4; i++) s[n][i] = 0.0f;
        #pragma unroll
        for (int np = 0; np < 4; np++) {
            #pragma unroll
            for (int kc = 0; kc < 4; kc++) {
                uint32_t off = (uint32_t)((np * 16 + krow) * 128 + kc * 32) + kcb;
                uint32_t kb[4], kl[4];
                ldsm_x4(bK + SWZ(off), kb);
                ldsm_x4(bKl + SWZ(off), kl);
                mma_f16(s[2*np],   qfh[kc], kb[0], kb[1]);
                mma_f16(s[2*np],   qfh[kc], kl[0], kl[1]);
                mma_f16(s[2*np],   qfl[kc], kb[0], kb[1]);
                mma_f16(s[2*np+1], qfh[kc], kb[2], kb[3]);
                mma_f16(s[2*np+1], qfh[kc], kl[2], kl[3]);
                mma_f16(s[2*np+1], qfl[kc], kb[2], kb[3]);
            }
        }

        // ---- mask + exp2 (scores already in log2 units) ----
        const unsigned int ma0 = mw0[t*2], mb0 = mw0[t*2+1];
        const unsigned int ma1 = mw1[t*2], mb1 = mw1[t*2+1];
        float p[8][4];
        const int cb2 = (lane & 3) * 2;
        #pragma unroll
        for (int n = 0; n < 8; n++) {
            int col = n * 8 + cb2;
            unsigned int w0 = (col < 32) ? ma0 : mb0;
            unsigned int w1 = (col < 32) ? ma1 : mb1;
            int sh = col & 31;
            p[n][0] = ((w0 >> sh)     & 1u) ? 0.0f : ex2(s[n][0]);
            p[n][1] = ((w0 >> (sh+1)) & 1u) ? 0.0f : ex2(s[n][1]);
            p[n][2] = ((w1 >> sh)     & 1u) ? 0.0f : ex2(s[n][2]);
            p[n][3] = ((w1 >> (sh+1)) & 1u) ? 0.0f : ex2(s[n][3]);
            lsum0 += p[n][0] + p[n][1];
            lsum1 += p[n][2] + p[n][3];
        }

        // ---- GEMM2: O += Ph·Vh (single term; fp16 residual terms cost
        //      ~2.3e-4 each by the R11 calibration — inside budget) ----
        #pragma unroll
        for (int kc = 0; kc < 4; kc++) {
            uint32_t ah[4];
            ah[0] = pkf16(p[2*kc][0],   p[2*kc][1]);
            ah[1] = pkf16(p[2*kc][2],   p[2*kc][3]);
            ah[2] = pkf16(p[2*kc+1][0], p[2*kc+1][1]);
            ah[3] = pkf16(p[2*kc+1][2], p[2*kc+1][3]);
            #pragma unroll
            for (int dp = 0; dp < 4; dp++) {
                uint32_t off = (uint32_t)((kc * 16 + vrow) * 128 + dp * 32) + vcb;
                uint32_t vh[4];
                ldsm_x4t(bV + SWZ(off), vh);
                mma_f16(o[2*dp],   ah, vh[0], vh[1]);
                mma_f16(o[2*dp+1], ah, vh[2], vh[3]);
            }
        }

        __syncthreads();                        // done reading buf[t&1]
        if (t + 2 < NTILES) {                   // prefetch t+2 into buf[t&1]
            size_t rb = (rowbase + (size_t)(t + 2) * KT) * ROWU4;
            uint32_t db = sb + (uint32_t)((t & 1) * STAGE);
            #pragma unroll
            for (int j = 0; j < 2; j++) {
                int i = tid + j * NTHREADS;
                cpa16(db + i * 16,         gKhi + rb + i);
                cpa16(db + 8192 + i * 16,  gKlo + rb + i);
                cpa16(db + 16384 + i * 16, gVhi + rb + i);
            }
        }
        CP_COMMIT();
        CP_WAIT1();                             // tile t+1 complete
        __syncthreads();
    }

    // ---- epilogue ----
    lsum0 += __shfl_xor_sync(0xffffffffu, lsum0, 1);
    lsum0 += __shfl_xor_sync(0xffffffffu, lsum0, 2);
    lsum1 += __shfl_xor_sync(0xffffffffu, lsum1, 1);
    lsum1 += __shfl_xor_sync(0xffffffffu, lsum1, 2);
    const float inv0 = (lsum0 > 0.0f) ? (1.0f / lsum0) : 0.0f;   // fully masked -> 0
    const float inv1 = (lsum1 > 0.0f) ? (1.0f / lsum1) : 0.0f;

    float* Ob = O + (size_t)bh * SLEN * HDIM;
    const int r0 = qt * BQ + wid * 16 + (lane >> 2);
    const int r1 = r0 + 8;
    #pragma unroll
    for (int n = 0; n < 8; n++) {
        int col = n * 8 + (lane & 3) * 2;
        *(float2*)(Ob + (size_t)r0 * HDIM + col) =
            make_float2(o[n][0] * inv0, o[n][1] * inv0);
        *(float2*)(Ob + (size_t)r1 * HDIM + col) =
            make_float2(o[n][2] * inv1, o[n][3] * inv1);
    }
}

extern "C" void kernel_launch(void* const* d_in, const int* in_sizes, int n_in,
                              void* d_out, int out_size)
{
    (void)in_sizes; (void)n_in; (void)out_size;
    const float* Q = (const float*)d_in[0];
    const float* K = (const float*)d_in[1];
    const float* V = (const float*)d_in[2];
    const int*   M = (const int*)d_in[3];
    float*       O = (float*)d_out;

    cudaFuncSetAttribute(sdpa_mma_kernel,
                         cudaFuncAttributeMaxDynamicSharedMemorySize, SM_TOTAL);

    pack_mask_kernel<<<MASK_WORDS / 256, 256>>>(M);
    dim3 pg(NROWCHUNKS / 256, 3);
    presplit_kernel<<<pg, 256>>>(Q, K, V);
    dim3 grid(NBH, SLEN / BQ);
    sdpa_mma_kernel<<<grid, NTHREADS, SM_TOTAL>>>(O);
}

// round 15
// speedup vs baseline: 2.6930x; 1.4064x over previous
#include <cuda_runtime.h>
#include <cuda_fp16.h>
#include <cstdint>

// ScaleDotProduct via mma.sync fp16 (HMMA): out = softmax(mask(Q K^T / 8)) V
// R15: pure-fp16 on BOTH GEMMs. Error model (calibrated R11, validated R14):
// each dropped fp16 residual term costs ~2.3e-4 output error; 4 dropped terms
// rss with measured base -> ~4.4e-4 vs 1e-3 threshold. MMA count halves.
// ex2-folded softmax; ballot-based mask pack; hi-only presplit images.

#define SLEN 2048
#define HDIM 64
#define NHEADS 16
#define NBH 32
#define BQ 128
#define KT 64
#define NTILES (SLEN / KT)
#define NTHREADS 256
#define MASK_WORDS (2 * SLEN * (SLEN / 32))
#define ROWU4 8                       // 64 fp16 = 128B = 8 uint4 per row
#define NROWCHUNKS (NBH * SLEN * ROWU4)

__device__ unsigned int g_maskbits[MASK_WORDS];
__device__ __align__(16) uint4 gQhi[NROWCHUNKS];
__device__ __align__(16) uint4 gKhi[NROWCHUNKS];
__device__ __align__(16) uint4 gVhi[NROWCHUNKS];

// stage = {Khi@0, Vhi@8K} = 16KB; two stages.
#define STAGE 16384
#define SM_TOTAL 32768

#define SWZ(o) ((o) ^ ((((uint32_t)(o)) >> 3) & 0x70))

__device__ __forceinline__ uint32_t smem_u32(const void* p) {
    uint32_t a;
    asm("{ .reg .u64 t; cvta.to.shared.u64 t, %1; cvt.u32.u64 %0, t; }"
        : "=r"(a) : "l"(p));
    return a;
}
__device__ __forceinline__ void ldsm_x4(uint32_t addr, uint32_t r[4]) {
    asm volatile("ldmatrix.sync.aligned.m8n8.x4.shared.b16 {%0,%1,%2,%3}, [%4];"
        : "=r"(r[0]), "=r"(r[1]), "=r"(r[2]), "=r"(r[3]) : "r"(addr));
}
__device__ __forceinline__ void ldsm_x4t(uint32_t addr, uint32_t r[4]) {
    asm volatile("ldmatrix.sync.aligned.m8n8.x4.trans.shared.b16 {%0,%1,%2,%3}, [%4];"
        : "=r"(r[0]), "=r"(r[1]), "=r"(r[2]), "=r"(r[3]) : "r"(addr));
}
__device__ __forceinline__ void mma_f16(float d[4], const uint32_t a[4],
                                        uint32_t b0, uint32_t b1) {
    asm volatile(
        "mma.sync.aligned.m16n8k16.row.col.f32.f16.f16.f32 "
        "{%0,%1,%2,%3}, {%4,%5,%6,%7}, {%8,%9}, {%0,%1,%2,%3};"
        : "+f"(d[0]), "+f"(d[1]), "+f"(d[2]), "+f"(d[3])
        : "r"(a[0]), "r"(a[1]), "r"(a[2]), "r"(a[3]), "r"(b0), "r"(b1));
}
__device__ __forceinline__ void cpa16(uint32_t dst, const void* src) {
    asm volatile("cp.async.cg.shared.global [%0], [%1], 16;"
                 :: "r"(dst), "l"(src) : "memory");
}
#define CP_COMMIT() asm volatile("cp.async.commit_group;" ::: "memory")
#define CP_WAIT0()  asm volatile("cp.async.wait_group 0;" ::: "memory")
#define CP_WAIT1()  asm volatile("cp.async.wait_group 1;" ::: "memory")

__device__ __forceinline__ float ex2(float x) {
    float r;
    asm("ex2.approx.f32 %0, %1;" : "=f"(r) : "f"(x));
    return r;
}
__device__ __forceinline__ uint32_t pkf16(float a, float b) {
    uint32_t r;
    asm("cvt.rn.f16x2.f32 %0, %1, %2;" : "=r"(r) : "f"(b), "f"(a));
    return r;
}

// ---------- pre-pass 1: mask int32 -> bits (warp-ballot, coalesced) ----------
__global__ void pack_mask_kernel(const int* __restrict__ M) {
    int idx = blockIdx.x * blockDim.x + threadIdx.x;   // one mask element
    unsigned int b = __ballot_sync(0xffffffffu, M[idx] != 0);
    if ((threadIdx.x & 31) == 0) g_maskbits[idx >> 5] = b;
}

// ---------- pre-pass 2: fp32 -> fp16 swizzled images (hi only) ----------
// Q pre-scaled by (1/8)*log2(e) so softmax is a bare ex2.
__global__ void presplit_kernel(const float* __restrict__ Q,
                                const float* __restrict__ K,
                                const float* __restrict__ V) {
    int idx = blockIdx.x * blockDim.x + threadIdx.x;
    if (idx >= NROWCHUNKS) return;
    int rg = idx >> 3;
    int c  = idx & 7;
    const float* src;
    uint4* dh;
    float sc;
    if (blockIdx.y == 0)      { src = Q; dh = gQhi; sc = 0.125f * 1.44269504f; }
    else if (blockIdx.y == 1) { src = K; dh = gKhi; sc = 1.0f; }
    else                      { src = V; dh = gVhi; sc = 1.0f; }
    const float4* s4 = (const float4*)(src + (size_t)rg * HDIM + c * 8);
    float4 a = s4[0], b = s4[1];
    uint4 hi = make_uint4(pkf16(a.x * sc, a.y * sc), pkf16(a.z * sc, a.w * sc),
                          pkf16(b.x * sc, b.y * sc), pkf16(b.z * sc, b.w * sc));
    int cs = c ^ (rg & 7);        // matches smem SWZ
    dh[(size_t)rg * 8 + cs] = hi;
}

// ---------- main kernel ----------
__global__ __launch_bounds__(NTHREADS, 2)
void sdpa_mma_kernel(float* __restrict__ O)
{
    extern __shared__ __align__(128) char smem[];
    const uint32_t sb = smem_u32(smem);
    const int tid  = threadIdx.x;
    const int lane = tid & 31;
    const int wid  = tid >> 5;

    const int bh = blockIdx.x;
    const int qt = blockIdx.y;
    const size_t rowbase = (size_t)bh * SLEN;

    // ---- prologue: Qhi -> buf0 ----
    {
        const uint4* qh = gQhi + (rowbase + (size_t)qt * BQ) * ROWU4;
        #pragma unroll
        for (int j = 0; j < 4; j++) {           // 1024 chunks / 256 thr
            int i = tid + j * NTHREADS;
            cpa16(sb + i * 16, qh + i);
        }
        CP_COMMIT();
        CP_WAIT0();
        __syncthreads();
    }

    // ---- Q A-fragments (constant across tiles) ----
    uint32_t qfh[4][4];
    {
        int qr = wid * 16 + (lane & 15);
        uint32_t cb = (uint32_t)((lane >> 4) * 16);
        #pragma unroll
        for (int kc = 0; kc < 4; kc++) {
            uint32_t off = (uint32_t)(qr * 128 + kc * 32) + cb;
            ldsm_x4(sb + SWZ(off), qfh[kc]);
        }
    }
    __syncthreads();

    // prefetch tile0 -> buf0, tile1 -> buf1 (separate groups)
    #pragma unroll
    for (int tt = 0; tt < 2; tt++) {
        size_t rb = (rowbase + (size_t)tt * KT) * ROWU4;
        uint32_t db = sb + (uint32_t)(tt * STAGE);
        #pragma unroll
        for (int j = 0; j < 2; j++) {           // 512 chunks / 256 thr per array
            int i = tid + j * NTHREADS;
            cpa16(db + i * 16,        gKhi + rb + i);
            cpa16(db + 8192 + i * 16, gVhi + rb + i);
        }
        CP_COMMIT();
    }
    CP_WAIT1();
    __syncthreads();

    float o[8][4];
    #pragma unroll
    for (int n = 0; n < 8; n++)
        #pragma unroll
        for (int i = 0; i < 4; i++) o[n][i] = 0.0f;
    float lsum0 = 0.0f, lsum1 = 0.0f;

    const int row0 = qt * BQ + wid * 16 + (lane >> 2);
    const unsigned int* mw0 = g_maskbits
        + (size_t)(bh / NHEADS) * SLEN * (SLEN / 32) + (size_t)row0 * (SLEN / 32);
    const unsigned int* mw1 = mw0 + 8 * (SLEN / 32);

    const int krow = (lane & 7) + ((lane >> 4) << 3);
    const uint32_t kcb = (uint32_t)(((lane >> 3) & 1) * 16);
    const int vrow = lane & 15;
    const uint32_t vcb = (uint32_t)((lane >> 4) * 16);

    for (int t = 0; t < NTILES; t++) {
        const uint32_t bK = sb + (uint32_t)((t & 1) * STAGE);
        const uint32_t bV = bK + 8192;

        // ---- GEMM1: S = Qh·Kh (pure fp16) ----
        float s[8][4];
        #pragma unroll
        for (int n = 0; n < 8; n++)
            #pragma unroll
            for (int i = 0; i < 4; i++) s[n][i] = 0.0f;
        #pragma unroll
        for (int np = 0; np < 4; np++) {
            #pragma unroll
            for (int kc = 0; kc < 4; kc++) {
                uint32_t off = (uint32_t)((np * 16 + krow) * 128 + kc * 32) + kcb;
                uint32_t kb[4];
                ldsm_x4(bK + SWZ(off), kb);
                mma_f16(s[2*np],   qfh[kc], kb[0], kb[1]);
                mma_f16(s[2*np+1], qfh[kc], kb[2], kb[3]);
            }
        }

        // ---- mask + exp2 (scores already in log2 units) ----
        const unsigned int ma0 = mw0[t*2], mb0 = mw0[t*2+1];
        const unsigned int ma1 = mw1[t*2], mb1 = mw1[t*2+1];
        float p[8][4];
        const int cb2 = (lane & 3) * 2;
        #pragma unroll
        for (int n = 0; n < 8; n++) {
            int col = n * 8 + cb2;
            unsigned int w0 = (col < 32) ? ma0 : mb0;
            unsigned int w1 = (col < 32) ? ma1 : mb1;
            int sh = col & 31;
            p[n][0] = ((w0 >> sh)     & 1u) ? 0.0f : ex2(s[n][0]);
            p[n][1] = ((w0 >> (sh+1)) & 1u) ? 0.0f : ex2(s[n][1]);
            p[n][2] = ((w1 >> sh)     & 1u) ? 0.0f : ex2(s[n][2]);
            p[n][3] = ((w1 >> (sh+1)) & 1u) ? 0.0f : ex2(s[n][3]);
            lsum0 += p[n][0] + p[n][1];
            lsum1 += p[n][2] + p[n][3];
        }

        // ---- GEMM2: O += Ph·Vh (pure fp16) ----
        #pragma unroll
        for (int kc = 0; kc < 4; kc++) {
            uint32_t ah[4];
            ah[0] = pkf16(p[2*kc][0],   p[2*kc][1]);
            ah[1] = pkf16(p[2*kc][2],   p[2*kc][3]);
            ah[2] = pkf16(p[2*kc+1][0], p[2*kc+1][1]);
            ah[3] = pkf16(p[2*kc+1][2], p[2*kc+1][3]);
            #pragma unroll
            for (int dp = 0; dp < 4; dp++) {
                uint32_t off = (uint32_t)((kc * 16 + vrow) * 128 + dp * 32) + vcb;
                uint32_t vh[4];
                ldsm_x4t(bV + SWZ(off), vh);
                mma_f16(o[2*dp],   ah, vh[0], vh[1]);
                mma_f16(o[2*dp+1], ah, vh[2], vh[3]);
            }
        }

        __syncthreads();                        // done reading buf[t&1]
        if (t + 2 < NTILES) {                   // prefetch t+2 into buf[t&1]
            size_t rb = (rowbase + (size_t)(t + 2) * KT) * ROWU4;
            uint32_t db = sb + (uint32_t)((t & 1) * STAGE);
            #pragma unroll
            for (int j = 0; j < 2; j++) {
                int i = tid + j * NTHREADS;
                cpa16(db + i * 16,        gKhi + rb + i);
                cpa16(db + 8192 + i * 16, gVhi + rb + i);
            }
        }
        CP_COMMIT();
        CP_WAIT1();                             // tile t+1 complete
        __syncthreads();
    }

    // ---- epilogue ----
    lsum0 += __shfl_xor_sync(0xffffffffu, lsum0, 1);
    lsum0 += __shfl_xor_sync(0xffffffffu, lsum0, 2);
    lsum1 += __shfl_xor_sync(0xffffffffu, lsum1, 1);
    lsum1 += __shfl_xor_sync(0xffffffffu, lsum1, 2);
    const float inv0 = (lsum0 > 0.0f) ? (1.0f / lsum0) : 0.0f;   // fully masked -> 0
    const float inv1 = (lsum1 > 0.0f) ? (1.0f / lsum1) : 0.0f;

    float* Ob = O + (size_t)bh * SLEN * HDIM;
    const int r0 = qt * BQ + wid * 16 + (lane >> 2);
    const int r1 = r0 + 8;
    #pragma unroll
    for (int n = 0; n < 8; n++) {
        int col = n * 8 + (lane & 3) * 2;
        *(float2*)(Ob + (size_t)r0 * HDIM + col) =
            make_float2(o[n][0] * inv0, o[n][1] * inv0);
        *(float2*)(Ob + (size_t)r1 * HDIM + col) =
            make_float2(o[n][2] * inv1, o[n][3] * inv1);
    }
}

extern "C" void kernel_launch(void* const* d_in, const int* in_sizes, int n_in,
                              void* d_out, int out_size)
{
    (void)in_sizes; (void)n_in; (void)out_size;
    const float* Q = (const float*)d_in[0];
    const float* K = (const float*)d_in[1];
    const float* V = (const float*)d_in[2];
    const int*   M = (const int*)d_in[3];
    float*       O = (float*)d_out;

    cudaFuncSetAttribute(sdpa_mma_kernel,
                         cudaFuncAttributeMaxDynamicSharedMemorySize, SM_TOTAL);

    pack_mask_kernel<<<(2 * SLEN * SLEN) / 256, 256>>>(M);
    dim3 pg(NROWCHUNKS / 256, 3);
    presplit_kernel<<<pg, 256>>>(Q, K, V);
    dim3 grid(NBH, SLEN / BQ);
    sdpa_mma_kernel<<<grid, NTHREADS, SM_TOTAL>>>(O);
}

// round 16
// speedup vs baseline: 2.9431x; 1.0929x over previous
#include <cuda_runtime.h>
#include <cuda_fp16.h>
#include <cstdint>

// ScaleDotProduct via mma.sync fp16 (HMMA): out = softmax(mask(Q K^T / 8)) V
// R16: hot loop identical to R15 (pure-fp16 GEMMs, ex2-folded softmax,
// rel_err 4.3e-4 with 2.3x margin). Pre-pass overhaul: warp-cooperative
// ballot mask pack (4x128B coalesced loads/warp), Q converted in-kernel
// (presplit now only K,V).

#define SLEN 2048
#define HDIM 64
#define NHEADS 16
#define NBH 32
#define BQ 128
#define KT 64
#define NTILES (SLEN / KT)
#define NTHREADS 256
#define MASK_WORDS (2 * SLEN * (SLEN / 32))
#define ROWU4 8                       // 64 fp16 = 128B = 8 uint4 per row
#define NROWCHUNKS (NBH * SLEN * ROWU4)

__device__ unsigned int g_maskbits[MASK_WORDS];
__device__ __align__(16) uint4 gKhi[NROWCHUNKS];
__device__ __align__(16) uint4 gVhi[NROWCHUNKS];

// stage = {Khi@0, Vhi@8K} = 16KB; two stages.
#define STAGE 16384
#define SM_TOTAL 32768

#define SWZ(o) ((o) ^ ((((uint32_t)(o)) >> 3) & 0x70))

__device__ __forceinline__ uint32_t smem_u32(const void* p) {
    uint32_t a;
    asm("{ .reg .u64 t; cvta.to.shared.u64 t, %1; cvt.u32.u64 %0, t; }"
        : "=r"(a) : "l"(p));
    return a;
}
__device__ __forceinline__ void ldsm_x4(uint32_t addr, uint32_t r[4]) {
    asm volatile("ldmatrix.sync.aligned.m8n8.x4.shared.b16 {%0,%1,%2,%3}, [%4];"
        : "=r"(r[0]), "=r"(r[1]), "=r"(r[2]), "=r"(r[3]) : "r"(addr));
}
__device__ __forceinline__ void ldsm_x4t(uint32_t addr, uint32_t r[4]) {
    asm volatile("ldmatrix.sync.aligned.m8n8.x4.trans.shared.b16 {%0,%1,%2,%3}, [%4];"
        : "=r"(r[0]), "=r"(r[1]), "=r"(r[2]), "=r"(r[3]) : "r"(addr));
}
__device__ __forceinline__ void mma_f16(float d[4], const uint32_t a[4],
                                        uint32_t b0, uint32_t b1) {
    asm volatile(
        "mma.sync.aligned.m16n8k16.row.col.f32.f16.f16.f32 "
        "{%0,%1,%2,%3}, {%4,%5,%6,%7}, {%8,%9}, {%0,%1,%2,%3};"
        : "+f"(d[0]), "+f"(d[1]), "+f"(d[2]), "+f"(d[3])
        : "r"(a[0]), "r"(a[1]), "r"(a[2]), "r"(a[3]), "r"(b0), "r"(b1));
}
__device__ __forceinline__ void cpa16(uint32_t dst, const void* src) {
    asm volatile("cp.async.cg.shared.global [%0], [%1], 16;"
                 :: "r"(dst), "l"(src) : "memory");
}
#define CP_COMMIT() asm volatile("cp.async.commit_group;" ::: "memory")
#define CP_WAIT1()  asm volatile("cp.async.wait_group 1;" ::: "memory")

__device__ __forceinline__ float ex2(float x) {
    float r;
    asm("ex2.approx.f32 %0, %1;" : "=f"(r) : "f"(x));
    return r;
}
__device__ __forceinline__ uint32_t pkf16(float a, float b) {
    uint32_t r;
    asm("cvt.rn.f16x2.f32 %0, %1, %2;" : "=r"(r) : "f"(b), "f"(a));
    return r;
}

// ---------- pre-pass 1: mask int32 -> bits (warp covers 128 ints) ----------
__global__ void pack_mask_kernel(const int* __restrict__ M) {
    int w = blockIdx.x * (blockDim.x >> 5) + (threadIdx.x >> 5);  // warp id
    int lane = threadIdx.x & 31;
    const int* p = M + (size_t)w * 128;
    unsigned int b0 = __ballot_sync(0xffffffffu, p[lane]      != 0);
    unsigned int b1 = __ballot_sync(0xffffffffu, p[lane + 32] != 0);
    unsigned int b2 = __ballot_sync(0xffffffffu, p[lane + 64] != 0);
    unsigned int b3 = __ballot_sync(0xffffffffu, p[lane + 96] != 0);
    if (lane == 0)
        *(uint4*)(g_maskbits + w * 4) = make_uint4(b0, b1, b2, b3);
}

// ---------- pre-pass 2: K/V fp32 -> fp16 swizzled images ----------
__global__ void presplit_kernel(const float* __restrict__ K,
                                const float* __restrict__ V) {
    int idx = blockIdx.x * blockDim.x + threadIdx.x;
    if (idx >= NROWCHUNKS) return;
    int rg = idx >> 3;
    int c  = idx & 7;
    const float* src = (blockIdx.y == 0) ? K : V;
    uint4* dh        = (blockIdx.y == 0) ? gKhi : gVhi;
    const float4* s4 = (const float4*)(src + (size_t)rg * HDIM + c * 8);
    float4 a = s4[0], b = s4[1];
    uint4 hi = make_uint4(pkf16(a.x, a.y), pkf16(a.z, a.w),
                          pkf16(b.x, b.y), pkf16(b.z, b.w));
    int cs = c ^ (rg & 7);        // matches smem SWZ
    dh[(size_t)rg * 8 + cs] = hi;
}

// ---------- main kernel ----------
__global__ __launch_bounds__(NTHREADS, 2)
void sdpa_mma_kernel(const float* __restrict__ Q, float* __restrict__ O)
{
    extern __shared__ __align__(128) char smem[];
    const uint32_t sb = smem_u32(smem);
    const int tid  = threadIdx.x;
    const int lane = tid & 31;
    const int wid  = tid >> 5;

    const int bh = blockIdx.x;
    const int qt = blockIdx.y;
    const size_t rowbase = (size_t)bh * SLEN;

    // ---- prologue: convert own Q tile fp32 -> fp16 smem image (buf0) ----
    {
        const float4* Qg = (const float4*)(Q + (rowbase + (size_t)qt * BQ) * HDIM);
        const float qsc = 0.125f * 1.44269504f;   // (1/8)*log2(e)
        #pragma unroll
        for (int j = 0; j < 8; j++) {             // 2048 float4 / 256 thr
            int idx = tid + j * NTHREADS;
            int r = idx >> 4, c4 = idx & 15;
            float4 q = Qg[idx];
            uint32_t sw = SWZ((uint32_t)(r * 128 + c4 * 8));
            *(uint2*)(smem + sw) = make_uint2(pkf16(q.x * qsc, q.y * qsc),
                                              pkf16(q.z * qsc, q.w * qsc));
        }
        __syncthreads();
    }

    // ---- Q A-fragments (constant across tiles) ----
    uint32_t qfh[4][4];
    {
        int qr = wid * 16 + (lane & 15);
        uint32_t cb = (uint32_t)((lane >> 4) * 16);
        #pragma unroll
        for (int kc = 0; kc < 4; kc++) {
            uint32_t off = (uint32_t)(qr * 128 + kc * 32) + cb;
            ldsm_x4(sb + SWZ(off), qfh[kc]);
        }
    }
    __syncthreads();                              // buf0 free for K/V tiles

    // prefetch tile0 -> buf0, tile1 -> buf1 (separate groups)
    #pragma unroll
    for (int tt = 0; tt < 2; tt++) {
        size_t rb = (rowbase + (size_t)tt * KT) * ROWU4;
        uint32_t db = sb + (uint32_t)(tt * STAGE);
        #pragma unroll
        for (int j = 0; j < 2; j++) {             // 512 chunks / 256 thr per array
            int i = tid + j * NTHREADS;
            cpa16(db + i * 16,        gKhi + rb + i);
            cpa16(db + 8192 + i * 16, gVhi + rb + i);
        }
        CP_COMMIT();
    }
    CP_WAIT1();
    __syncthreads();

    float o[8][4];
    #pragma unroll
    for (int n = 0; n < 8; n++)
        #pragma unroll
        for (int i = 0; i < 4; i++) o[n][i] = 0.0f;
    float lsum0 = 0.0f, lsum1 = 0.0f;

    const int row0 = qt * BQ + wid * 16 + (lane >> 2);
    const unsigned int* mw0 = g_maskbits
        + (size_t)(bh / NHEADS) * SLEN * (SLEN / 32) + (size_t)row0 * (SLEN / 32);
    const unsigned int* mw1 = mw0 + 8 * (SLEN / 32);

    const int krow = (lane & 7) + ((lane >> 4) << 3);
    const uint32_t kcb = (uint32_t)(((lane >> 3) & 1) * 16);
    const int vrow = lane & 15;
    const uint32_t vcb = (uint32_t)((lane >> 4) * 16);

    for (int t = 0; t < NTILES; t++) {
        const uint32_t bK = sb + (uint32_t)((t & 1) * STAGE);
        const uint32_t bV = bK + 8192;

        // ---- GEMM1: S = Qh·Kh (pure fp16) ----
        float s[8][4];
        #pragma unroll
        for (int n = 0; n < 8; n++)
            #pragma unroll
            for (int i = 0; i < 4; i++) s[n][i] = 0.0f;
        #pragma unroll
        for (int np = 0; np < 4; np++) {
            #pragma unroll
            for (int kc = 0; kc < 4; kc++) {
                uint32_t off = (uint32_t)((np * 16 + krow) * 128 + kc * 32) + kcb;
                uint32_t kb[4];
                ldsm_x4(bK + SWZ(off), kb);
                mma_f16(s[2*np],   qfh[kc], kb[0], kb[1]);
                mma_f16(s[2*np+1], qfh[kc], kb[2], kb[3]);
            }
        }

        // ---- mask + exp2 (scores already in log2 units) ----
        const unsigned int ma0 = mw0[t*2], mb0 = mw0[t*2+1];
        const unsigned int ma1 = mw1[t*2], mb1 = mw1[t*2+1];
        float p[8][4];
        const int cb2 = (lane & 3) * 2;
        #pragma unroll
        for (int n = 0; n < 8; n++) {
            int col = n * 8 + cb2;
            unsigned int w0 = (col < 32) ? ma0 : mb0;
            unsigned int w1 = (col < 32) ? ma1 : mb1;
            int sh = col & 31;
            p[n][0] = ((w0 >> sh)     & 1u) ? 0.0f : ex2(s[n][0]);
            p[n][1] = ((w0 >> (sh+1)) & 1u) ? 0.0f : ex2(s[n][1]);
            p[n][2] = ((w1 >> sh)     & 1u) ? 0.0f : ex2(s[n][2]);
            p[n][3] = ((w1 >> (sh+1)) & 1u) ? 0.0f : ex2(s[n][3]);
            lsum0 += p[n][0] + p[n][1];
            lsum1 += p[n][2] + p[n][3];
        }

        // ---- GEMM2: O += Ph·Vh (pure fp16) ----
        #pragma unroll
        for (int kc = 0; kc < 4; kc++) {
            uint32_t ah[4];
            ah[0] = pkf16(p[2*kc][0],   p[2*kc][1]);
            ah[1] = pkf16(p[2*kc][2],   p[2*kc][3]);
            ah[2] = pkf16(p[2*kc+1][0], p[2*kc+1][1]);
            ah[3] = pkf16(p[2*kc+1][2], p[2*kc+1][3]);
            #pragma unroll
            for (int dp = 0; dp < 4; dp++) {
                uint32_t off = (uint32_t)((kc * 16 + vrow) * 128 + dp * 32) + vcb;
                uint32_t vh[4];
                ldsm_x4t(bV + SWZ(off), vh);
                mma_f16(o[2*dp],   ah, vh[0], vh[1]);
                mma_f16(o[2*dp+1], ah, vh[2], vh[3]);
            }
        }

        __syncthreads();                        // done reading buf[t&1]
        if (t + 2 < NTILES) {                   // prefetch t+2 into buf[t&1]
            size_t rb = (rowbase + (size_t)(t + 2) * KT) * ROWU4;
            uint32_t db = sb + (uint32_t)((t & 1) * STAGE);
            #pragma unroll
            for (int j = 0; j < 2; j++) {
                int i = tid + j * NTHREADS;
                cpa16(db + i * 16,        gKhi + rb + i);
                cpa16(db + 8192 + i * 16, gVhi + rb + i);
            }
        }
        CP_COMMIT();
        CP_WAIT1();                             // tile t+1 complete
        __syncthreads();
    }

    // ---- epilogue ----
    lsum0 += __shfl_xor_sync(0xffffffffu, lsum0, 1);
    lsum0 += __shfl_xor_sync(0xffffffffu, lsum0, 2);
    lsum1 += __shfl_xor_sync(0xffffffffu, lsum1, 1);
    lsum1 += __shfl_xor_sync(0xffffffffu, lsum1, 2);
    const float inv0 = (lsum0 > 0.0f) ? (1.0f / lsum0) : 0.0f;   // fully masked -> 0
    const float inv1 = (lsum1 > 0.0f) ? (1.0f / lsum1) : 0.0f;

    float* Ob = O + rowbase * HDIM;
    const int r0 = qt * BQ + wid * 16 + (lane >> 2);
    const int r1 = r0 + 8;
    #pragma unroll
    for (int n = 0; n < 8; n++) {
        int col = n * 8 + (lane & 3) * 2;
        *(float2*)(Ob + (size_t)r0 * HDIM + col) =
            make_float2(o[n][0] * inv0, o[n][1] * inv0);
        *(float2*)(Ob + (size_t)r1 * HDIM + col) =
            make_float2(o[n][2] * inv1, o[n][3] * inv1);
    }
}

extern "C" void kernel_launch(void* const* d_in, const int* in_sizes, int n_in,
                              void* d_out, int out_size)
{
    (void)in_sizes; (void)n_in; (void)out_size;
    const float* Q = (const float*)d_in[0];
    const float* K = (const float*)d_in[1];
    const float* V = (const float*)d_in[2];
    const int*   M = (const int*)d_in[3];
    float*       O = (float*)d_out;

    cudaFuncSetAttribute(sdpa_mma_kernel,
                         cudaFuncAttributeMaxDynamicSharedMemorySize, SM_TOTAL);

    // 65536 warps cover 2*S*S ints; 8 warps per 256-thr block
    pack_mask_kernel<<<(2 * SLEN * SLEN / 128) / 8, 256>>>(M);
    dim3 pg(NROWCHUNKS / 256, 2);
    presplit_kernel<<<pg, 256>>>(K, V);
    dim3 grid(NBH, SLEN / BQ);
    sdpa_mma_kernel<<<grid, NTHREADS, SM_TOTAL>>>(Q, O);
}